// round 6
// baseline (speedup 1.0000x reference)
#include <cuda_runtime.h>
#include <cuda_bf16.h>
#include <cstdint>

// ---------------------------------------------------------------------------
// PCA-whitening norm. x: [64,64,128,128] fp32.
//   1. gram_kernel : partial Gram + per-channel sums  (cp.async double-buffered)
//   2. reduce_kernel: 4-way parallel partial reduction
//   3. eigen_kernel : 32 x (power iter + Rayleigh + deflation) -> W, off
//   4. apply_kernel : out = W @ x + off   (sync-free LDG streaming, L1 reuse)
// ---------------------------------------------------------------------------

#define CCH   64
#define HWSZ  16384
#define RS    132
#define NTILES 8192
#define G1    296
#define G2    444
#define KEIG  32
#define EPSV  1e-5f

__device__ float g_pg[G1 * 4096];
__device__ float g_ps[G1 * 64];
__device__ float g_gram[4096];
__device__ float g_S[64];
__device__ float g_W[4096];
__device__ float g_off[64];

__device__ __forceinline__ void ffma2(unsigned long long& d,
                                      unsigned long long a,
                                      unsigned long long b) {
    asm("fma.rn.f32x2 %0, %1, %2, %0;" : "+l"(d) : "l"(a), "l"(b));
}
__device__ __forceinline__ unsigned long long pack2(float s) {
    unsigned long long d;
    asm("mov.b64 %0, {%1, %1};" : "=l"(d) : "f"(s));
    return d;
}
__device__ __forceinline__ void unpack2(unsigned long long d, float& lo, float& hi) {
    asm("mov.b64 {%0, %1}, %2;" : "=f"(lo), "=f"(hi) : "l"(d));
}
__device__ __forceinline__ void cpa16(void* s, const void* g) {
    uint32_t sa = (uint32_t)__cvta_generic_to_shared(s);
    asm volatile("cp.async.cg.shared.global [%0], [%1], 16;" :: "r"(sa), "l"(g));
}
#define CP_COMMIT asm volatile("cp.async.commit_group;")
#define CP_WAIT1  asm volatile("cp.async.wait_group 1;")

// ---------------------------------------------------------------------------
// Pass 1: partial Gram + channel sums (unchanged from R2 — rework next round).
// ---------------------------------------------------------------------------
__global__ void __launch_bounds__(256, 2)
gram_kernel(const float* __restrict__ x) {
    extern __shared__ float sm[];
    float* buf0 = sm;
    float* buf1 = sm + CCH * RS;

    const int t    = threadIdx.x;
    const int g2   = t >> 7;
    const int tg   = t & 127;
    const int i    = tg >> 4;
    const int j    = tg & 15;
    const int wa   = t >> 5;
    const int lane = t & 31;
    const int mb   = g2 * 64;
    const int srow = t >> 2;
    const int scol = (t & 3) * 32;

    unsigned long long acc[8][4];
#pragma unroll
    for (int r = 0; r < 8; r++)
#pragma unroll
        for (int c = 0; c < 4; c++) acc[r][c] = 0ULL;
    float csum = 0.0f;

    {
        const int tau = blockIdx.x;
        const int n = tau >> 7, m0 = (tau & 127) << 7;
        const float* base = x + (size_t)(n * CCH) * HWSZ + m0;
#pragma unroll
        for (int q = 0; q < 8; q++) {
            const int c = q * 8 + wa;
            cpa16(buf0 + c * RS + lane * 4, base + (size_t)c * HWSZ + lane * 4);
        }
    }
    CP_COMMIT;

    int parity = 0;
    for (int tau = blockIdx.x; tau < NTILES; tau += G1) {
        const int taun = tau + G1;
        float* nb = parity ? buf0 : buf1;
        if (taun < NTILES) {
            const int n = taun >> 7, m0 = (taun & 127) << 7;
            const float* base = x + (size_t)(n * CCH) * HWSZ + m0;
#pragma unroll
            for (int q = 0; q < 8; q++) {
                const int c = q * 8 + wa;
                cpa16(nb + c * RS + lane * 4, base + (size_t)c * HWSZ + lane * 4);
            }
        }
        CP_COMMIT;
        CP_WAIT1;
        __syncthreads();
        const float* tb = parity ? buf1 : buf0;

        {
            float s = 0.0f;
#pragma unroll
            for (int k = 0; k < 8; k++) {
                const float4 v4 = *(const float4*)(tb + srow * RS + scol + 4 * k);
                s += (v4.x + v4.y) + (v4.z + v4.w);
            }
            csum += s;
        }

#pragma unroll 2
        for (int mg = 0; mg < 16; mg++) {
            const int m = mb + 4 * mg;
            longlong2 av[8], bv[4];
#pragma unroll
            for (int r = 0; r < 8; r++)
                av[r] = *(const longlong2*)(tb + (i + 8 * r) * RS + m);
#pragma unroll
            for (int c = 0; c < 4; c++)
                bv[c] = *(const longlong2*)(tb + (j + 16 * c) * RS + m);
#pragma unroll
            for (int r = 0; r < 8; r++)
#pragma unroll
                for (int c = 0; c < 4; c++) {
                    ffma2(acc[r][c], (unsigned long long)av[r].x,
                                      (unsigned long long)bv[c].x);
                    ffma2(acc[r][c], (unsigned long long)av[r].y,
                                      (unsigned long long)bv[c].y);
                }
        }
        __syncthreads();
        parity ^= 1;
    }

    csum += __shfl_down_sync(0xffffffffu, csum, 2);
    csum += __shfl_down_sync(0xffffffffu, csum, 1);
    if ((t & 3) == 0) g_ps[blockIdx.x * 64 + srow] = csum;

    if (g2 == 0) {
#pragma unroll
        for (int r = 0; r < 8; r++)
#pragma unroll
            for (int c = 0; c < 4; c++) {
                float lo, hi; unpack2(acc[r][c], lo, hi);
                buf0[(i + 8 * r) * 65 + (j + 16 * c)] = lo + hi;
            }
    }
    __syncthreads();
    if (g2 == 1) {
#pragma unroll
        for (int r = 0; r < 8; r++)
#pragma unroll
            for (int c = 0; c < 4; c++) {
                float lo, hi; unpack2(acc[r][c], lo, hi);
                buf0[(i + 8 * r) * 65 + (j + 16 * c)] += lo + hi;
            }
    }
    __syncthreads();
    float* pg = g_pg + (size_t)blockIdx.x * 4096;
#pragma unroll
    for (int kk = 0; kk < 16; kk++) {
        const int idx = t + kk * 256;
        pg[idx] = buf0[(idx >> 6) * 65 + (idx & 63)];
    }
}

// ---------------------------------------------------------------------------
// Pass 1b: 4 threads per output, fixed-order chunks (deterministic).
// ---------------------------------------------------------------------------
__global__ void reduce_kernel() {
    const int b = blockIdx.x, t = threadIdx.x;
    if (b < 64) {
        const int o = b * 64 + (t >> 2);     // output index
        const int s = t & 3;                 // chunk id
        const int g0 = s * 74;
        float acc = 0.0f;
#pragma unroll 2
        for (int g = g0; g < g0 + 74; g++) acc += g_pg[(size_t)g * 4096 + o];
        acc += __shfl_down_sync(0xffffffffu, acc, 2);
        acc += __shfl_down_sync(0xffffffffu, acc, 1);
        if (s == 0) g_gram[o] = acc;
    } else if (t < 64) {
        float s = 0.0f;
        for (int g = 0; g < G1; g++) s += g_ps[g * 64 + t];
        g_S[t] = s;
    }
}

// ---------------------------------------------------------------------------
// Eigen kernel: single block, 256 threads (unchanged).
// ---------------------------------------------------------------------------
__global__ void eigen_kernel(const float* __restrict__ weight,
                             const float* __restrict__ bias,
                             const float* __restrict__ vinit) {
    __shared__ float cov[64 * 65];
    __shared__ float v[64];
    __shared__ float wv[64];
    __shared__ float red[256];
    __shared__ float mu[64];
    __shared__ float Vs[KEIG * 64];
    __shared__ float lamArr[KEIG];
    __shared__ float invs[KEIG];
    __shared__ float scal;

    const int t = threadIdx.x;
    const float invM = 1.0f / 1048576.0f;

    if (t < 64) mu[t] = g_S[t] * invM;
    __syncthreads();
    for (int idx = t; idx < 4096; idx += 256) {
        const int ii = idx >> 6, jj = idx & 63;
        float c = g_gram[idx] * invM - mu[ii] * mu[jj];
        if (ii == jj) c += EPSV;
        cov[ii * 65 + jj] = c;
    }
    const int row = t & 63, part = t >> 6;
    __syncthreads();

    for (int k = 0; k < KEIG; k++) {
        if (t < 64) v[t] = vinit[k * 64 + t];
        __syncthreads();
        for (int it = 0; it < 10; it++) {
            float p = 0.0f;
#pragma unroll
            for (int q = 0; q < 16; q++)
                p += cov[row * 65 + part * 16 + q] * v[part * 16 + q];
            red[part * 64 + row] = p;
            __syncthreads();
            if (part == 0)
                v[row] = (red[row] + red[64 + row]) + (red[128 + row] + red[192 + row]);
            __syncthreads();
        }
        if (t < 64) red[t] = v[t] * v[t];
        __syncthreads();
        if (t < 32) {
            float s = red[t] + red[t + 32];
#pragma unroll
            for (int off = 16; off > 0; off >>= 1)
                s += __shfl_down_sync(0xffffffffu, s, off);
            if (t == 0) scal = 1.0f / sqrtf(s);
        }
        __syncthreads();
        if (t < 64) v[t] *= scal;
        __syncthreads();
        {
            float p = 0.0f;
#pragma unroll
            for (int q = 0; q < 16; q++)
                p += cov[row * 65 + part * 16 + q] * v[part * 16 + q];
            red[part * 64 + row] = p;
            __syncthreads();
            if (part == 0)
                wv[row] = (red[row] + red[64 + row]) + (red[128 + row] + red[192 + row]);
            __syncthreads();
        }
        if (t < 64) red[t] = v[t] * wv[t];
        __syncthreads();
        if (t < 32) {
            float s = red[t] + red[t + 32];
#pragma unroll
            for (int off = 16; off > 0; off >>= 1)
                s += __shfl_down_sync(0xffffffffu, s, off);
            if (t == 0) scal = s;
        }
        __syncthreads();
        const float lam = scal;
        if (t == 0) lamArr[k] = lam;
        if (t < 64) Vs[k * 64 + t] = v[t];
        __syncthreads();
        for (int idx = t; idx < 4096; idx += 256)
            cov[(idx >> 6) * 65 + (idx & 63)] -= lam * v[idx >> 6] * v[idx & 63];
        __syncthreads();
    }

    if (t < KEIG) invs[t] = 1.0f / sqrtf(lamArr[t] + EPSV);
    __syncthreads();
    for (int idx = t; idx < 4096; idx += 256) {
        const int c = idx >> 6, cp = idx & 63;
        float s = 0.0f;
#pragma unroll
        for (int k = 0; k < KEIG; k++)
            s += Vs[k * 64 + c] * invs[k] * Vs[k * 64 + cp];
        g_W[idx] = weight[c] * s;
    }
    __syncthreads();
    if (t < 64) {
        float s = bias[t];
        for (int cp = 0; cp < 64; cp++) s -= g_W[t * 64 + cp] * mu[cp];
        g_off[t] = s;
    }
}

// ---------------------------------------------------------------------------
// Pass 2: out = W @ x + off.  Sync-free streaming version.
// Warp w owns channels 8w..8w+7 (warp-uniform -> W LDS broadcast).
// Lane l owns columns 4l..4l+3 (one LDG.128 per cp, x tile stays L1-resident
// across the 8 warps of the block). 3 blocks/SM, no __syncthreads in mainloop.
// Per cp per warp: 1 LDG.128 + 2 LDS.128 + 16 FFMA2.
// ---------------------------------------------------------------------------
__global__ void __launch_bounds__(256, 3)
apply_kernel(const float* __restrict__ x, float* __restrict__ out) {
    __shared__ unsigned long long sWp[4096];   // [cp][ch] pre-packed pairs
    __shared__ float soff[64];

    const int t = threadIdx.x;
    const int w = t >> 5;
    const int l = t & 31;
    const int ch0 = 8 * w;

    for (int idx = t; idx < 4096; idx += 256)
        sWp[idx] = pack2(g_W[(idx & 63) * 64 + (idx >> 6)]);  // sWp[cp*64+c]
    if (t < 64) soff[t] = g_off[t];
    __syncthreads();   // once, before mainloop

    for (int tau = blockIdx.x; tau < NTILES; tau += G2) {
        const int n = tau >> 7, m0 = (tau & 127) << 7;
        const float* base = x + (size_t)(n * CCH) * HWSZ + m0 + 4 * l;

        unsigned long long acc[8][2];
#pragma unroll
        for (int r = 0; r < 8; r++) {
            const unsigned long long po = pack2(soff[ch0 + r]);
            acc[r][0] = po; acc[r][1] = po;
        }

#pragma unroll 4
        for (int cp = 0; cp < 64; cp++) {
            const ulonglong2 xv = *(const ulonglong2*)(base + (size_t)cp * HWSZ);
            const ulonglong2 wA = *(const ulonglong2*)(sWp + cp * 64 + ch0);
            const ulonglong2 wB = *(const ulonglong2*)(sWp + cp * 64 + ch0 + 2);
            const ulonglong2 wC = *(const ulonglong2*)(sWp + cp * 64 + ch0 + 4);
            const ulonglong2 wD = *(const ulonglong2*)(sWp + cp * 64 + ch0 + 6);
            ffma2(acc[0][0], wA.x, xv.x); ffma2(acc[0][1], wA.x, xv.y);
            ffma2(acc[1][0], wA.y, xv.x); ffma2(acc[1][1], wA.y, xv.y);
            ffma2(acc[2][0], wB.x, xv.x); ffma2(acc[2][1], wB.x, xv.y);
            ffma2(acc[3][0], wB.y, xv.x); ffma2(acc[3][1], wB.y, xv.y);
            ffma2(acc[4][0], wC.x, xv.x); ffma2(acc[4][1], wC.x, xv.y);
            ffma2(acc[5][0], wC.y, xv.x); ffma2(acc[5][1], wC.y, xv.y);
            ffma2(acc[6][0], wD.x, xv.x); ffma2(acc[6][1], wD.x, xv.y);
            ffma2(acc[7][0], wD.y, xv.x); ffma2(acc[7][1], wD.y, xv.y);
        }

        float* ob = out + (size_t)(n * CCH) * HWSZ + m0 + 4 * l;
#pragma unroll
        for (int r = 0; r < 8; r++) {
            ulonglong2 s;
            s.x = acc[r][0]; s.y = acc[r][1];
            *(ulonglong2*)(ob + (size_t)(ch0 + r) * HWSZ) = s;
        }
    }
}

// ---------------------------------------------------------------------------
#define GRAM_SMEM (2 * CCH * RS * 4)

extern "C" void kernel_launch(void* const* d_in, const int* in_sizes, int n_in,
                              void* d_out, int out_size) {
    const float* x      = (const float*)d_in[0];
    const float* weight = (const float*)d_in[1];
    const float* bias   = (const float*)d_in[2];
    const float* vinit  = (const float*)d_in[3];
    float* out = (float*)d_out;

    cudaFuncSetAttribute(gram_kernel,
                         cudaFuncAttributeMaxDynamicSharedMemorySize, GRAM_SMEM);

    gram_kernel<<<G1, 256, GRAM_SMEM>>>(x);
    reduce_kernel<<<65, 256>>>();
    eigen_kernel<<<1, 256>>>(weight, bias, vinit);
    apply_kernel<<<G2, 256>>>(x, out);
}

// round 9
// speedup vs baseline: 2.1678x; 2.1678x over previous
#include <cuda_runtime.h>
#include <cuda_bf16.h>
#include <cstdint>

// ---------------------------------------------------------------------------
// PCA-whitening norm. x: [64,64,128,128] fp32.  mma.sync (HMMA) version.
//   1. gram_mma  : P1 = xh@xh^T, P2 = xl@xh^T per block (reg-resident accum)
//   2. reduce_kernel : gram = sum(P1 + P2 + P2^T), channel sums
//   3. eigen_kernel  : -> g_W, g_off (unchanged)
//   4. apply_mma : out = W@x + off, K=192 bf16-split HMMA
// ---------------------------------------------------------------------------

#define CCH    64
#define HWSZ   16384
#define NTILES 8192
#define GBLK   444          // persistent grid for both mma kernels (3/SM)
#define KEIG   32
#define EPSV   1e-5f

__device__ float g_p1[GBLK * 4096];
__device__ float g_p2[GBLK * 4096];
__device__ float g_ps[GBLK * 64];
__device__ float g_gram[4096];
__device__ float g_S[64];
__device__ float g_W[4096];
__device__ float g_off[64];

// ---------------- helpers ----------------
__device__ __forceinline__ uint32_t smem_u32(const void* p) {
    return (uint32_t)__cvta_generic_to_shared(p);
}
// pack two f32 -> bf16x2 (a -> low half, b -> high half)
__device__ __forceinline__ uint32_t cvt_bf2(float a, float b) {
    uint32_t d;
    asm("cvt.rn.bf16x2.f32 %0, %1, %2;" : "=r"(d) : "f"(b), "f"(a));
    return d;
}
__device__ __forceinline__ void ldsm4(uint32_t* r, uint32_t addr) {
    asm volatile("ldmatrix.sync.aligned.m8n8.x4.shared.b16 {%0,%1,%2,%3}, [%4];"
                 : "=r"(r[0]), "=r"(r[1]), "=r"(r[2]), "=r"(r[3]) : "r"(addr));
}
__device__ __forceinline__ void mma16816(float* d, const uint32_t* a,
                                         uint32_t b0, uint32_t b1) {
    asm volatile("mma.sync.aligned.m16n8k16.row.col.f32.bf16.bf16.f32 "
                 "{%0,%1,%2,%3}, {%4,%5,%6,%7}, {%8,%9}, {%0,%1,%2,%3};"
                 : "+f"(d[0]), "+f"(d[1]), "+f"(d[2]), "+f"(d[3])
                 : "r"(a[0]), "r"(a[1]), "r"(a[2]), "r"(a[3]), "r"(b0), "r"(b1));
}
__device__ __forceinline__ void sts64(uint32_t addr, uint32_t r0, uint32_t r1) {
    asm volatile("st.shared.v2.b32 [%0], {%1, %2};" :: "r"(addr), "r"(r0), "r"(r1));
}
__device__ __forceinline__ void sts128(uint32_t addr, uint32_t r0, uint32_t r1,
                                       uint32_t r2, uint32_t r3) {
    asm volatile("st.shared.v4.b32 [%0], {%1, %2, %3, %4};"
                 :: "r"(addr), "r"(r0), "r"(r1), "r"(r2), "r"(r3));
}

// ---------------------------------------------------------------------------
// Pass 1: gram via HMMA.  Block 128 thr (4 warps), grid GBLK persistent.
// smem: Xh/Xl bf16 [ch 64][px 128] rows 256B, 16B-chunk swizzle ^(ch&7).
// Warp w: full m=64 (ch), n-slice = ch' in [16w, 16w+16).  K = pixels.
// P1 += xh@xh^T, P2 += xl@xh^T, accumulators in registers across tiles.
// ---------------------------------------------------------------------------
__global__ void __launch_bounds__(128, 3)
gram_mma(const float* __restrict__ x) {
    __shared__ __align__(16) uint8_t sXh[64 * 256];
    __shared__ __align__(16) uint8_t sXl[64 * 256];

    const int t = threadIdx.x;
    const int w = t >> 5;
    const int lane = t & 31;

    float P1[4][2][4], P2[4][2][4];
#pragma unroll
    for (int mf = 0; mf < 4; mf++)
#pragma unroll
        for (int nf = 0; nf < 2; nf++)
#pragma unroll
            for (int e = 0; e < 4; e++) { P1[mf][nf][e] = 0.f; P2[mf][nf][e] = 0.f; }
    float csum[16];
#pragma unroll
    for (int q = 0; q < 16; q++) csum[q] = 0.f;

    // ldmatrix lane-address precompute
    const int rs = lane & 7;                     // swizzle key (row & 7)
    const uint32_t xh32 = smem_u32(sXh), xl32 = smem_u32(sXl);
    uint32_t aRowH[4], aRowL[4];
#pragma unroll
    for (int mf = 0; mf < 4; mf++) {
        const int row = (lane & 15) + mf * 16;
        aRowH[mf] = xh32 + row * 256;
        aRowL[mf] = xl32 + row * 256;
    }
    const int bRow = w * 16 + (lane & 7) + ((lane >> 4) << 3);
    const uint32_t bRowA = xh32 + bRow * 256;
    const int aCadd = (lane >> 4);               // chunk add for A quads
    const int bCadd = ((lane >> 3) & 1);         // chunk add for B quads

    for (int tau = blockIdx.x; tau < NTILES; tau += GBLK) {
        const int n = tau >> 7, m0 = (tau & 127) << 7;

        // ---- convert fp32 -> bf16 h/l into swizzled smem; channel sums ----
        {
            const float* bx = x + (size_t)(n * CCH) * HWSZ + m0 + 4 * lane;
#pragma unroll 4
            for (int q = 0; q < 16; q++) {
                const int ch = w + 4 * q;
                const float4 f4 = *(const float4*)(bx + (size_t)ch * HWSZ);
                csum[q] += (f4.x + f4.y) + (f4.z + f4.w);
                const uint32_t h0 = cvt_bf2(f4.x, f4.y);
                const uint32_t h1 = cvt_bf2(f4.z, f4.w);
                const uint32_t l0 = cvt_bf2(f4.x - __uint_as_float(h0 << 16),
                                            f4.y - __uint_as_float(h0 & 0xFFFF0000u));
                const uint32_t l1 = cvt_bf2(f4.z - __uint_as_float(h1 << 16),
                                            f4.w - __uint_as_float(h1 & 0xFFFF0000u));
                const uint32_t off = ch * 256 + 16 * ((lane >> 1) ^ (ch & 7)) + 8 * (lane & 1);
                sts64(xh32 + off, h0, h1);
                sts64(xl32 + off, l0, l1);
            }
        }
        __syncthreads();

        // ---- HMMA mainloop: 8 K-steps of 16 pixels ----
#pragma unroll
        for (int ks = 0; ks < 8; ks++) {
            const uint32_t offA = 16 * ((ks * 2 + aCadd) ^ rs);
            const uint32_t offB = 16 * ((ks * 2 + bCadd) ^ rs);
            uint32_t b[4];
            ldsm4(b, bRowA + offB);
            uint32_t ah[4][4], al[4][4];
#pragma unroll
            for (int mf = 0; mf < 4; mf++) ldsm4(ah[mf], aRowH[mf] + offA);
#pragma unroll
            for (int mf = 0; mf < 4; mf++) ldsm4(al[mf], aRowL[mf] + offA);
#pragma unroll
            for (int mf = 0; mf < 4; mf++) {
                mma16816(P1[mf][0], ah[mf], b[0], b[1]);
                mma16816(P1[mf][1], ah[mf], b[2], b[3]);
                mma16816(P2[mf][0], al[mf], b[0], b[1]);
                mma16816(P2[mf][1], al[mf], b[2], b[3]);
            }
        }
        __syncthreads();
    }

    // ---- epilogue: write register partials + channel sums ----
    float* p1 = g_p1 + (size_t)blockIdx.x * 4096;
    float* p2 = g_p2 + (size_t)blockIdx.x * 4096;
#pragma unroll
    for (int mf = 0; mf < 4; mf++)
#pragma unroll
        for (int nf = 0; nf < 2; nf++) {
            const int i = mf * 16 + (lane >> 2);
            const int j = w * 16 + nf * 8 + (lane & 3) * 2;
            *(float2*)(p1 + i * 64 + j)       = make_float2(P1[mf][nf][0], P1[mf][nf][1]);
            *(float2*)(p1 + (i + 8) * 64 + j) = make_float2(P1[mf][nf][2], P1[mf][nf][3]);
            *(float2*)(p2 + i * 64 + j)       = make_float2(P2[mf][nf][0], P2[mf][nf][1]);
            *(float2*)(p2 + (i + 8) * 64 + j) = make_float2(P2[mf][nf][2], P2[mf][nf][3]);
        }
#pragma unroll
    for (int q = 0; q < 16; q++) {
        float s = csum[q];
#pragma unroll
        for (int off = 16; off > 0; off >>= 1)
            s += __shfl_down_sync(0xffffffffu, s, off);
        if (lane == 0) g_ps[blockIdx.x * 64 + (w + 4 * q)] = s;
    }
}

// ---------------------------------------------------------------------------
// Pass 1b: gram[i][j] = sum_g P1 + P2 + P2^T ; channel sums. Deterministic.
// ---------------------------------------------------------------------------
__global__ void reduce_kernel() {
    const int b = blockIdx.x, t = threadIdx.x;
    if (b < 256) {
        const int o = b * 16 + (t >> 3);
        const int i = o >> 6, j = o & 63;
        const int s = t & 7;
        const int g0 = s * 56;
        const int g1 = (g0 + 56 < GBLK) ? g0 + 56 : GBLK;
        const int ot = j * 64 + i;
        float acc = 0.f;
        for (int g = g0; g < g1; g++) {
            const size_t base = (size_t)g * 4096;
            acc += g_p1[base + o] + g_p2[base + o] + g_p2[base + ot];
        }
        acc += __shfl_down_sync(0xffffffffu, acc, 4);
        acc += __shfl_down_sync(0xffffffffu, acc, 2);
        acc += __shfl_down_sync(0xffffffffu, acc, 1);
        if (s == 0) g_gram[o] = acc;
    } else if (t < 64) {
        float s = 0.f;
        for (int g = 0; g < GBLK; g++) s += g_ps[g * 64 + t];
        g_S[t] = s;
    }
}

// ---------------------------------------------------------------------------
// Eigen kernel (unchanged): cov -> 32x(power iter, Rayleigh, deflate) -> W, off
// ---------------------------------------------------------------------------
__global__ void eigen_kernel(const float* __restrict__ weight,
                             const float* __restrict__ bias,
                             const float* __restrict__ vinit) {
    __shared__ float cov[64 * 65];
    __shared__ float v[64];
    __shared__ float wv[64];
    __shared__ float red[256];
    __shared__ float mu[64];
    __shared__ float Vs[KEIG * 64];
    __shared__ float lamArr[KEIG];
    __shared__ float invs[KEIG];
    __shared__ float scal;

    const int t = threadIdx.x;
    const float invM = 1.0f / 1048576.0f;

    if (t < 64) mu[t] = g_S[t] * invM;
    __syncthreads();
    for (int idx = t; idx < 4096; idx += 256) {
        const int ii = idx >> 6, jj = idx & 63;
        float c = g_gram[idx] * invM - mu[ii] * mu[jj];
        if (ii == jj) c += EPSV;
        cov[ii * 65 + jj] = c;
    }
    const int row = t & 63, part = t >> 6;
    __syncthreads();

    for (int k = 0; k < KEIG; k++) {
        if (t < 64) v[t] = vinit[k * 64 + t];
        __syncthreads();
        for (int it = 0; it < 10; it++) {
            float p = 0.0f;
#pragma unroll
            for (int q = 0; q < 16; q++)
                p += cov[row * 65 + part * 16 + q] * v[part * 16 + q];
            red[part * 64 + row] = p;
            __syncthreads();
            if (part == 0)
                v[row] = (red[row] + red[64 + row]) + (red[128 + row] + red[192 + row]);
            __syncthreads();
        }
        if (t < 64) red[t] = v[t] * v[t];
        __syncthreads();
        if (t < 32) {
            float s = red[t] + red[t + 32];
#pragma unroll
            for (int off = 16; off > 0; off >>= 1)
                s += __shfl_down_sync(0xffffffffu, s, off);
            if (t == 0) scal = 1.0f / sqrtf(s);
        }
        __syncthreads();
        if (t < 64) v[t] *= scal;
        __syncthreads();
        {
            float p = 0.0f;
#pragma unroll
            for (int q = 0; q < 16; q++)
                p += cov[row * 65 + part * 16 + q] * v[part * 16 + q];
            red[part * 64 + row] = p;
            __syncthreads();
            if (part == 0)
                wv[row] = (red[row] + red[64 + row]) + (red[128 + row] + red[192 + row]);
            __syncthreads();
        }
        if (t < 64) red[t] = v[t] * wv[t];
        __syncthreads();
        if (t < 32) {
            float s = red[t] + red[t + 32];
#pragma unroll
            for (int off = 16; off > 0; off >>= 1)
                s += __shfl_down_sync(0xffffffffu, s, off);
            if (t == 0) scal = s;
        }
        __syncthreads();
        const float lam = scal;
        if (t == 0) lamArr[k] = lam;
        if (t < 64) Vs[k * 64 + t] = v[t];
        __syncthreads();
        for (int idx = t; idx < 4096; idx += 256)
            cov[(idx >> 6) * 65 + (idx & 63)] -= lam * v[idx >> 6] * v[idx & 63];
        __syncthreads();
    }

    if (t < KEIG) invs[t] = 1.0f / sqrtf(lamArr[t] + EPSV);
    __syncthreads();
    for (int idx = t; idx < 4096; idx += 256) {
        const int c = idx >> 6, cp = idx & 63;
        float s = 0.0f;
#pragma unroll
        for (int k = 0; k < KEIG; k++)
            s += Vs[k * 64 + c] * invs[k] * Vs[k * 64 + cp];
        g_W[idx] = weight[c] * s;
    }
    __syncthreads();
    if (t < 64) {
        float s = bias[t];
        for (int cp = 0; cp < 64; cp++) s -= g_W[t * 64 + cp] * mu[cp];
        g_off[t] = s;
    }
}

// ---------------------------------------------------------------------------
// Pass 2: apply via HMMA.  Block 128 thr (4 warps), grid GBLK persistent.
// A = W: [cout 64][k 192] rows 400B (seg0 Wh, seg1 Wl, seg2 Wh dup).
// B = x tile: [px 128][ch 64] bf16 rows 128B, swizzle ^(px&7); Xh + Xl.
// Warp w: n-slice pixels [32w, 32w+32), m = all 64 cout.  K = 192.
// ---------------------------------------------------------------------------
#define W_OFF    0
#define XH_OFF   25600
#define XL_OFF   41984
#define SOFF_OFF 58368
#define AP_SMEM  58624

__global__ void __launch_bounds__(128, 3)
apply_mma(const float* __restrict__ x, float* __restrict__ out) {
    extern __shared__ __align__(16) uint8_t smem[];
    const int t = threadIdx.x;
    const int w = t >> 5;
    const int lane = t & 31;

    // ---- build A = [Wh|Wl|Wh] rows, soff ----
    for (int idx = t; idx < 4096; idx += 128) {
        const int cout = idx >> 6, cin = idx & 63;
        const float wv = g_W[idx];
        const __nv_bfloat16 hb = __float2bfloat16(wv);
        const __nv_bfloat16 lb = __float2bfloat16(wv - __bfloat162float(hb));
        uint8_t* rowp = smem + W_OFF + cout * 400;
        *(__nv_bfloat16*)(rowp + cin * 2)       = hb;
        *(__nv_bfloat16*)(rowp + 128 + cin * 2) = lb;
        *(__nv_bfloat16*)(rowp + 256 + cin * 2) = hb;
    }
    if (t < 64) *(float*)(smem + SOFF_OFF + 4 * t) = g_off[t];
    __syncthreads();

    // lane addressing
    const int rs = lane & 7;
    const uint32_t sw32 = smem_u32(smem + W_OFF);
    const uint32_t xh32 = smem_u32(smem + XH_OFF);
    const uint32_t xl32 = smem_u32(smem + XL_OFF);
    uint32_t aAddr[4];
#pragma unroll
    for (int mf = 0; mf < 4; mf++)
        aAddr[mf] = sw32 + ((lane & 15) + mf * 16) * 400 + (lane >> 4) * 16;
    uint32_t bRowOff[2];
#pragma unroll
    for (int nf = 0; nf < 2; nf++) {
        const int row = w * 32 + nf * 16 + (lane & 7) + ((lane >> 4) << 3);
        bRowOff[nf] = row * 128;
    }
    const int bCadd = ((lane >> 3) & 1);
    const float* soff = (const float*)(smem + SOFF_OFF);
    float offv[4][2];
#pragma unroll
    for (int mf = 0; mf < 4; mf++) {
        offv[mf][0] = soff[mf * 16 + (lane >> 2)];
        offv[mf][1] = soff[mf * 16 + (lane >> 2) + 8];
    }

    for (int tau = blockIdx.x; tau < NTILES; tau += GBLK) {
        const int n = tau >> 7, m0 = (tau & 127) << 7;

        // ---- convert: pixel t, 64 channels -> Xh/Xl rows (swizzled) ----
        {
            const float* bx = x + (size_t)(n * CCH) * HWSZ + m0 + t;
            const uint32_t rowh = xh32 + t * 128, rowl = xl32 + t * 128;
            const int ts = t & 7;
#pragma unroll
            for (int hh = 0; hh < 2; hh++) {
                uint32_t h[16], l[16];
#pragma unroll
                for (int i = 0; i < 16; i++) {
                    const int ch = hh * 32 + 2 * i;
                    const float a = bx[(size_t)ch * HWSZ];
                    const float b = bx[(size_t)(ch + 1) * HWSZ];
                    h[i] = cvt_bf2(a, b);
                    l[i] = cvt_bf2(a - __uint_as_float(h[i] << 16),
                                   b - __uint_as_float(h[i] & 0xFFFF0000u));
                }
#pragma unroll
                for (int j = 0; j < 4; j++) {
                    const uint32_t so = 16 * ((hh * 4 + j) ^ ts);
                    sts128(rowh + so, h[4 * j], h[4 * j + 1], h[4 * j + 2], h[4 * j + 3]);
                    sts128(rowl + so, l[4 * j], l[4 * j + 1], l[4 * j + 2], l[4 * j + 3]);
                }
            }
        }
        __syncthreads();

        // ---- acc init with offsets ----
        float acc[4][4][4];
#pragma unroll
        for (int mf = 0; mf < 4; mf++)
#pragma unroll
            for (int nfr = 0; nfr < 4; nfr++) {
                acc[mf][nfr][0] = offv[mf][0]; acc[mf][nfr][1] = offv[mf][0];
                acc[mf][nfr][2] = offv[mf][1]; acc[mf][nfr][3] = offv[mf][1];
            }

        // ---- HMMA mainloop: 12 K-steps of 16 ----
#pragma unroll
        for (int ks = 0; ks < 12; ks++) {
            const uint32_t xb = (ks < 8) ? xh32 : xl32;
            const int kk = ks & 3;
            uint32_t a[4][4];
#pragma unroll
            for (int mf = 0; mf < 4; mf++) ldsm4(a[mf], aAddr[mf] + ks * 32);
            uint32_t b[2][4];
#pragma unroll
            for (int nf = 0; nf < 2; nf++) {
                const uint32_t addr = xb + bRowOff[nf] + 16 * ((kk * 2 + bCadd) ^ rs);
                ldsm4(b[nf], addr);
            }
#pragma unroll
            for (int mf = 0; mf < 4; mf++)
#pragma unroll
                for (int nf = 0; nf < 2; nf++) {
                    mma16816(acc[mf][2 * nf],     a[mf], b[nf][0], b[nf][1]);
                    mma16816(acc[mf][2 * nf + 1], a[mf], b[nf][2], b[nf][3]);
                }
        }

        // ---- epilogue: out[cout][px] ----
        float* ob = out + (size_t)(n * CCH) * HWSZ + m0 + w * 32 + (lane & 3) * 2;
#pragma unroll
        for (int mf = 0; mf < 4; mf++) {
            const int cout = mf * 16 + (lane >> 2);
#pragma unroll
            for (int nfr = 0; nfr < 4; nfr++) {
                float* p = ob + nfr * 8;
                *(float2*)(p + (size_t)cout * HWSZ)       = make_float2(acc[mf][nfr][0], acc[mf][nfr][1]);
                *(float2*)(p + (size_t)(cout + 8) * HWSZ) = make_float2(acc[mf][nfr][2], acc[mf][nfr][3]);
            }
        }
        __syncthreads();
    }
}

// ---------------------------------------------------------------------------
extern "C" void kernel_launch(void* const* d_in, const int* in_sizes, int n_in,
                              void* d_out, int out_size) {
    const float* x      = (const float*)d_in[0];
    const float* weight = (const float*)d_in[1];
    const float* bias   = (const float*)d_in[2];
    const float* vinit  = (const float*)d_in[3];
    float* out = (float*)d_out;

    cudaFuncSetAttribute(apply_mma,
                         cudaFuncAttributeMaxDynamicSharedMemorySize, AP_SMEM);

    gram_mma<<<GBLK, 128>>>(x);
    reduce_kernel<<<257, 128>>>();
    eigen_kernel<<<1, 256>>>(weight, bias, vinit);
    apply_mma<<<GBLK, 128, AP_SMEM>>>(x, out);
}

// round 10
// speedup vs baseline: 2.3899x; 1.1025x over previous
#include <cuda_runtime.h>
#include <cuda_bf16.h>
#include <cstdint>

// ---------------------------------------------------------------------------
// PCA-whitening norm. x: [64,64,128,128] fp32.  HMMA version, pipelined.
//   1. gram_mma  : cp.async-staged fp32 -> bf16 h/l -> P1=xh@xh^T, P2=xl@xh^T
//   2. reduce_kernel : gram = sum(P1 + P2 + P2^T), channel sums
//   3. eigen_kernel  : -> g_W, g_off
//   4. apply_mma : out = W@x + off, K=192 bf16-split HMMA, [ch][px] B via
//                  ldmatrix.trans, LDG.128 conversion.
// ---------------------------------------------------------------------------

#define CCH    64
#define HWSZ   16384
#define NTILES 8192
#define GR     296           // gram grid (2/SM)
#define GA     444           // apply grid (3/SM)
#define KEIG   32
#define EPSV   1e-5f

__device__ float g_p1[GR * 4096];
__device__ float g_p2[GR * 4096];
__device__ float g_ps[GR * 64];
__device__ float g_gram[4096];
__device__ float g_S[64];
__device__ float g_W[4096];
__device__ float g_off[64];

// ---------------- helpers ----------------
__device__ __forceinline__ uint32_t smem_u32(const void* p) {
    return (uint32_t)__cvta_generic_to_shared(p);
}
__device__ __forceinline__ uint32_t cvt_bf2(float a, float b) {
    uint32_t d;
    asm("cvt.rn.bf16x2.f32 %0, %1, %2;" : "=r"(d) : "f"(b), "f"(a));
    return d;
}
__device__ __forceinline__ void ldsm4(uint32_t* r, uint32_t addr) {
    asm volatile("ldmatrix.sync.aligned.m8n8.x4.shared.b16 {%0,%1,%2,%3}, [%4];"
                 : "=r"(r[0]), "=r"(r[1]), "=r"(r[2]), "=r"(r[3]) : "r"(addr));
}
__device__ __forceinline__ void ldsm4t(uint32_t* r, uint32_t addr) {
    asm volatile("ldmatrix.sync.aligned.m8n8.x4.trans.shared.b16 {%0,%1,%2,%3}, [%4];"
                 : "=r"(r[0]), "=r"(r[1]), "=r"(r[2]), "=r"(r[3]) : "r"(addr));
}
__device__ __forceinline__ void mma16816(float* d, const uint32_t* a,
                                         uint32_t b0, uint32_t b1) {
    asm volatile("mma.sync.aligned.m16n8k16.row.col.f32.bf16.bf16.f32 "
                 "{%0,%1,%2,%3}, {%4,%5,%6,%7}, {%8,%9}, {%0,%1,%2,%3};"
                 : "+f"(d[0]), "+f"(d[1]), "+f"(d[2]), "+f"(d[3])
                 : "r"(a[0]), "r"(a[1]), "r"(a[2]), "r"(a[3]), "r"(b0), "r"(b1));
}
__device__ __forceinline__ void sts64(uint32_t addr, uint32_t r0, uint32_t r1) {
    asm volatile("st.shared.v2.b32 [%0], {%1, %2};" :: "r"(addr), "r"(r0), "r"(r1));
}
__device__ __forceinline__ void cpa16(void* s, const void* g) {
    uint32_t sa = (uint32_t)__cvta_generic_to_shared(s);
    asm volatile("cp.async.cg.shared.global [%0], [%1], 16;" :: "r"(sa), "l"(g));
}
#define CP_COMMIT asm volatile("cp.async.commit_group;")
#define CP_WAIT1  asm volatile("cp.async.wait_group 1;")

// ---------------------------------------------------------------------------
// Pass 1: gram, cp.async pipelined.  Block 128 thr, grid GR (2/SM).
// smem: F0/F1 fp32 [ch 64][px 128] (32KB each), XH/XL bf16 [ch][px] swizzled.
// Warp w: m = all 64 ch, n-slice ch' in [16w, 16w+16).
// ---------------------------------------------------------------------------
#define GF0    0
#define GF1    32768
#define GXH    65536
#define GXL    81920
#define G_SMEM 98304

__global__ void __launch_bounds__(128, 2)
gram_mma(const float* __restrict__ x) {
    extern __shared__ __align__(16) uint8_t smem[];
    const int t = threadIdx.x;
    const int w = t >> 5;
    const int lane = t & 31;

    float P1[4][2][4], P2[4][2][4];
#pragma unroll
    for (int mf = 0; mf < 4; mf++)
#pragma unroll
        for (int nf = 0; nf < 2; nf++)
#pragma unroll
            for (int e = 0; e < 4; e++) { P1[mf][nf][e] = 0.f; P2[mf][nf][e] = 0.f; }
    float csum[16];
#pragma unroll
    for (int q = 0; q < 16; q++) csum[q] = 0.f;

    const int rs = lane & 7;
    const uint32_t xh32 = smem_u32(smem + GXH), xl32 = smem_u32(smem + GXL);
    uint32_t aRowH[4], aRowL[4];
#pragma unroll
    for (int mf = 0; mf < 4; mf++) {
        const int row = (lane & 15) + mf * 16;
        aRowH[mf] = xh32 + row * 256;
        aRowL[mf] = xl32 + row * 256;
    }
    const int bRow = w * 16 + (lane & 7) + ((lane >> 4) << 3);
    const uint32_t bRowA = xh32 + bRow * 256;
    const int aCadd = (lane >> 4);
    const int bCadd = ((lane >> 3) & 1);

    // prologue: stage tile0 -> F0
    {
        const int tau = blockIdx.x;
        const int n = tau >> 7, m0 = (tau & 127) << 7;
        const float* base = x + (size_t)(n * CCH) * HWSZ + m0;
#pragma unroll
        for (int i = 0; i < 16; i++) {
            const int chunk = t + 128 * i;
            const int ch = chunk >> 5, pc = chunk & 31;
            cpa16(smem + GF0 + ch * 512 + pc * 16, base + (size_t)ch * HWSZ + pc * 4);
        }
    }
    CP_COMMIT;

    int parity = 0;
    for (int tau = blockIdx.x; tau < NTILES; tau += GR) {
        const int taun = tau + GR;
        uint8_t* nb = smem + (parity ? GF0 : GF1);
        if (taun < NTILES) {
            const int n = taun >> 7, m0 = (taun & 127) << 7;
            const float* base = x + (size_t)(n * CCH) * HWSZ + m0;
#pragma unroll
            for (int i = 0; i < 16; i++) {
                const int chunk = t + 128 * i;
                const int ch = chunk >> 5, pc = chunk & 31;
                cpa16(nb + ch * 512 + pc * 16, base + (size_t)ch * HWSZ + pc * 4);
            }
        }
        CP_COMMIT;
        CP_WAIT1;
        __syncthreads();
        const float* fb = (const float*)(smem + (parity ? GF1 : GF0));

        // ---- convert from staged fp32 (conflict-free LDS.128) ----
#pragma unroll
        for (int q = 0; q < 16; q++) {
            const int ch = w + 4 * q;
            const float4 f4 = *(const float4*)(fb + ch * 128 + 4 * lane);
            csum[q] += (f4.x + f4.y) + (f4.z + f4.w);
            const uint32_t h0 = cvt_bf2(f4.x, f4.y);
            const uint32_t h1 = cvt_bf2(f4.z, f4.w);
            const uint32_t l0 = cvt_bf2(f4.x - __uint_as_float(h0 << 16),
                                        f4.y - __uint_as_float(h0 & 0xFFFF0000u));
            const uint32_t l1 = cvt_bf2(f4.z - __uint_as_float(h1 << 16),
                                        f4.w - __uint_as_float(h1 & 0xFFFF0000u));
            const uint32_t so = ch * 256 + 16 * ((lane >> 1) ^ (ch & 7)) + 8 * (lane & 1);
            sts64(xh32 + so, h0, h1);
            sts64(xl32 + so, l0, l1);
        }
        __syncthreads();

        // ---- HMMA mainloop: 8 K-steps of 16 pixels ----
#pragma unroll
        for (int ks = 0; ks < 8; ks++) {
            const uint32_t offA = 16 * ((ks * 2 + aCadd) ^ rs);
            const uint32_t offB = 16 * ((ks * 2 + bCadd) ^ rs);
            uint32_t b[4];
            ldsm4(b, bRowA + offB);
            uint32_t ah[4][4], al[4][4];
#pragma unroll
            for (int mf = 0; mf < 4; mf++) ldsm4(ah[mf], aRowH[mf] + offA);
#pragma unroll
            for (int mf = 0; mf < 4; mf++) ldsm4(al[mf], aRowL[mf] + offA);
#pragma unroll
            for (int mf = 0; mf < 4; mf++) {
                mma16816(P1[mf][0], ah[mf], b[0], b[1]);
                mma16816(P1[mf][1], ah[mf], b[2], b[3]);
                mma16816(P2[mf][0], al[mf], b[0], b[1]);
                mma16816(P2[mf][1], al[mf], b[2], b[3]);
            }
        }
        __syncthreads();
        parity ^= 1;
    }

    // ---- epilogue ----
    float* p1 = g_p1 + (size_t)blockIdx.x * 4096;
    float* p2 = g_p2 + (size_t)blockIdx.x * 4096;
#pragma unroll
    for (int mf = 0; mf < 4; mf++)
#pragma unroll
        for (int nf = 0; nf < 2; nf++) {
            const int i = mf * 16 + (lane >> 2);
            const int j = w * 16 + nf * 8 + (lane & 3) * 2;
            *(float2*)(p1 + i * 64 + j)       = make_float2(P1[mf][nf][0], P1[mf][nf][1]);
            *(float2*)(p1 + (i + 8) * 64 + j) = make_float2(P1[mf][nf][2], P1[mf][nf][3]);
            *(float2*)(p2 + i * 64 + j)       = make_float2(P2[mf][nf][0], P2[mf][nf][1]);
            *(float2*)(p2 + (i + 8) * 64 + j) = make_float2(P2[mf][nf][2], P2[mf][nf][3]);
        }
#pragma unroll
    for (int q = 0; q < 16; q++) {
        float s = csum[q];
#pragma unroll
        for (int off = 16; off > 0; off >>= 1)
            s += __shfl_down_sync(0xffffffffu, s, off);
        if (lane == 0) g_ps[blockIdx.x * 64 + (w + 4 * q)] = s;
    }
}

// ---------------------------------------------------------------------------
// Pass 1b: gram[i][j] = sum_g P1 + P2 + P2^T ; channel sums. 296 = 8*37.
// ---------------------------------------------------------------------------
__global__ void reduce_kernel() {
    const int b = blockIdx.x, t = threadIdx.x;
    if (b < 256) {
        const int o = b * 16 + (t >> 3);
        const int i = o >> 6, j = o & 63;
        const int s = t & 7;
        const int g0 = s * 37;
        const int ot = j * 64 + i;
        float acc = 0.f;
        for (int g = g0; g < g0 + 37; g++) {
            const size_t base = (size_t)g * 4096;
            acc += g_p1[base + o] + g_p2[base + o] + g_p2[base + ot];
        }
        acc += __shfl_down_sync(0xffffffffu, acc, 4);
        acc += __shfl_down_sync(0xffffffffu, acc, 2);
        acc += __shfl_down_sync(0xffffffffu, acc, 1);
        if (s == 0) g_gram[o] = acc;
    } else if (t < 64) {
        float s = 0.f;
        for (int g = 0; g < GR; g++) s += g_ps[g * 64 + t];
        g_S[t] = s;
    }
}

// ---------------------------------------------------------------------------
// Eigen kernel (unchanged).
// ---------------------------------------------------------------------------
__global__ void eigen_kernel(const float* __restrict__ weight,
                             const float* __restrict__ bias,
                             const float* __restrict__ vinit) {
    __shared__ float cov[64 * 65];
    __shared__ float v[64];
    __shared__ float wv[64];
    __shared__ float red[256];
    __shared__ float mu[64];
    __shared__ float Vs[KEIG * 64];
    __shared__ float lamArr[KEIG];
    __shared__ float invs[KEIG];
    __shared__ float scal;

    const int t = threadIdx.x;
    const float invM = 1.0f / 1048576.0f;

    if (t < 64) mu[t] = g_S[t] * invM;
    __syncthreads();
    for (int idx = t; idx < 4096; idx += 256) {
        const int ii = idx >> 6, jj = idx & 63;
        float c = g_gram[idx] * invM - mu[ii] * mu[jj];
        if (ii == jj) c += EPSV;
        cov[ii * 65 + jj] = c;
    }
    const int row = t & 63, part = t >> 6;
    __syncthreads();

    for (int k = 0; k < KEIG; k++) {
        if (t < 64) v[t] = vinit[k * 64 + t];
        __syncthreads();
        for (int it = 0; it < 10; it++) {
            float p = 0.0f;
#pragma unroll
            for (int q = 0; q < 16; q++)
                p += cov[row * 65 + part * 16 + q] * v[part * 16 + q];
            red[part * 64 + row] = p;
            __syncthreads();
            if (part == 0)
                v[row] = (red[row] + red[64 + row]) + (red[128 + row] + red[192 + row]);
            __syncthreads();
        }
        if (t < 64) red[t] = v[t] * v[t];
        __syncthreads();
        if (t < 32) {
            float s = red[t] + red[t + 32];
#pragma unroll
            for (int off = 16; off > 0; off >>= 1)
                s += __shfl_down_sync(0xffffffffu, s, off);
            if (t == 0) scal = 1.0f / sqrtf(s);
        }
        __syncthreads();
        if (t < 64) v[t] *= scal;
        __syncthreads();
        {
            float p = 0.0f;
#pragma unroll
            for (int q = 0; q < 16; q++)
                p += cov[row * 65 + part * 16 + q] * v[part * 16 + q];
            red[part * 64 + row] = p;
            __syncthreads();
            if (part == 0)
                wv[row] = (red[row] + red[64 + row]) + (red[128 + row] + red[192 + row]);
            __syncthreads();
        }
        if (t < 64) red[t] = v[t] * wv[t];
        __syncthreads();
        if (t < 32) {
            float s = red[t] + red[t + 32];
#pragma unroll
            for (int off = 16; off > 0; off >>= 1)
                s += __shfl_down_sync(0xffffffffu, s, off);
            if (t == 0) scal = s;
        }
        __syncthreads();
        const float lam = scal;
        if (t == 0) lamArr[k] = lam;
        if (t < 64) Vs[k * 64 + t] = v[t];
        __syncthreads();
        for (int idx = t; idx < 4096; idx += 256)
            cov[(idx >> 6) * 65 + (idx & 63)] -= lam * v[idx >> 6] * v[idx & 63];
        __syncthreads();
    }

    if (t < KEIG) invs[t] = 1.0f / sqrtf(lamArr[t] + EPSV);
    __syncthreads();
    for (int idx = t; idx < 4096; idx += 256) {
        const int c = idx >> 6, cp = idx & 63;
        float s = 0.0f;
#pragma unroll
        for (int k = 0; k < KEIG; k++)
            s += Vs[k * 64 + c] * invs[k] * Vs[k * 64 + cp];
        g_W[idx] = weight[c] * s;
    }
    __syncthreads();
    if (t < 64) {
        float s = bias[t];
        for (int cp = 0; cp < 64; cp++) s -= g_W[t * 64 + cp] * mu[cp];
        g_off[t] = s;
    }
}

// ---------------------------------------------------------------------------
// Pass 2: apply via HMMA.  Block 128 thr, grid GA (3/SM).
// A = W: [cout 64][k 192] rows 400B (Wh|Wl|Wh).
// B = x: bf16 [ch 64][px 128] rows 256B swizzled ^(ch&7); frags via
//       ldmatrix.x4.trans.  Conversion: warp owns ch rows, LDG.128 per lane.
// ---------------------------------------------------------------------------
#define W_OFF    0
#define XH_OFF   25600
#define XL_OFF   41984
#define SOFF_OFF 58368
#define AP_SMEM  58624

__global__ void __launch_bounds__(128, 3)
apply_mma(const float* __restrict__ x, float* __restrict__ out) {
    extern __shared__ __align__(16) uint8_t smem[];
    const int t = threadIdx.x;
    const int w = t >> 5;
    const int lane = t & 31;

    // ---- build A = [Wh|Wl|Wh] rows, soff ----
    for (int idx = t; idx < 4096; idx += 128) {
        const int cout = idx >> 6, cin = idx & 63;
        const float wv = g_W[idx];
        const __nv_bfloat16 hb = __float2bfloat16(wv);
        const __nv_bfloat16 lb = __float2bfloat16(wv - __bfloat162float(hb));
        uint8_t* rowp = smem + W_OFF + cout * 400;
        *(__nv_bfloat16*)(rowp + cin * 2)       = hb;
        *(__nv_bfloat16*)(rowp + 128 + cin * 2) = lb;
        *(__nv_bfloat16*)(rowp + 256 + cin * 2) = hb;
    }
    if (t < 64) *(float*)(smem + SOFF_OFF + 4 * t) = g_off[t];
    __syncthreads();

    const int rs = lane & 7;
    const uint32_t sw32 = smem_u32(smem + W_OFF);
    const uint32_t xh32 = smem_u32(smem + XH_OFF);
    const uint32_t xl32 = smem_u32(smem + XL_OFF);
    uint32_t aAddr[4];
#pragma unroll
    for (int mf = 0; mf < 4; mf++)
        aAddr[mf] = sw32 + ((lane & 15) + mf * 16) * 400 + (lane >> 4) * 16;
    // B (trans) addressing: ch = (ks&3)*16 + bChOff, px chunk = cb + 2*nf
    const uint32_t bChOff = (uint32_t)((lane & 7) + 8 * ((lane >> 3) & 1));
    const int cb = w * 4 + (lane >> 4);
    const float* soff = (const float*)(smem + SOFF_OFF);
    float offv[4][2];
#pragma unroll
    for (int mf = 0; mf < 4; mf++) {
        offv[mf][0] = soff[mf * 16 + (lane >> 2)];
        offv[mf][1] = soff[mf * 16 + (lane >> 2) + 8];
    }

    for (int tau = blockIdx.x; tau < NTILES; tau += GA) {
        const int n = tau >> 7, m0 = (tau & 127) << 7;

        // ---- convert: warp owns ch rows (w+4q), lane = 4 px, LDG.128 ----
        {
            const float* bx = x + (size_t)(n * CCH) * HWSZ + m0 + 4 * lane;
#pragma unroll 8
            for (int q = 0; q < 16; q++) {
                const int ch = w + 4 * q;
                const float4 f4 = *(const float4*)(bx + (size_t)ch * HWSZ);
                const uint32_t h0 = cvt_bf2(f4.x, f4.y);
                const uint32_t h1 = cvt_bf2(f4.z, f4.w);
                const uint32_t l0 = cvt_bf2(f4.x - __uint_as_float(h0 << 16),
                                            f4.y - __uint_as_float(h0 & 0xFFFF0000u));
                const uint32_t l1 = cvt_bf2(f4.z - __uint_as_float(h1 << 16),
                                            f4.w - __uint_as_float(h1 & 0xFFFF0000u));
                const uint32_t so = ch * 256 + 16 * ((lane >> 1) ^ (ch & 7)) + 8 * (lane & 1);
                sts64(xh32 + so, h0, h1);
                sts64(xl32 + so, l0, l1);
            }
        }
        __syncthreads();

        // ---- acc init with offsets ----
        float acc[4][4][4];
#pragma unroll
        for (int mf = 0; mf < 4; mf++)
#pragma unroll
            for (int nfr = 0; nfr < 4; nfr++) {
                acc[mf][nfr][0] = offv[mf][0]; acc[mf][nfr][1] = offv[mf][0];
                acc[mf][nfr][2] = offv[mf][1]; acc[mf][nfr][3] = offv[mf][1];
            }

        // ---- HMMA mainloop: 12 K-steps of 16 (Wh.xh, Wl.xh, Wh.xl) ----
#pragma unroll
        for (int ks = 0; ks < 12; ks++) {
            const uint32_t xb = (ks < 8) ? xh32 : xl32;
            const uint32_t chRow = ((uint32_t)(ks & 3) * 16 + bChOff) * 256;
            uint32_t a[4][4];
#pragma unroll
            for (int mf = 0; mf < 4; mf++) ldsm4(a[mf], aAddr[mf] + ks * 32);
            uint32_t b[2][4];
#pragma unroll
            for (int nf = 0; nf < 2; nf++)
                ldsm4t(b[nf], xb + chRow + 16 * ((cb + 2 * nf) ^ rs));
#pragma unroll
            for (int mf = 0; mf < 4; mf++)
#pragma unroll
                for (int nf = 0; nf < 2; nf++) {
                    mma16816(acc[mf][2 * nf],     a[mf], b[nf][0], b[nf][1]);
                    mma16816(acc[mf][2 * nf + 1], a[mf], b[nf][2], b[nf][3]);
                }
        }

        // ---- epilogue: out[cout][px] ----
        float* ob = out + (size_t)(n * CCH) * HWSZ + m0 + w * 32 + (lane & 3) * 2;
#pragma unroll
        for (int mf = 0; mf < 4; mf++) {
            const int cout = mf * 16 + (lane >> 2);
#pragma unroll
            for (int nfr = 0; nfr < 4; nfr++) {
                float* p = ob + nfr * 8;
                *(float2*)(p + (size_t)cout * HWSZ)       = make_float2(acc[mf][nfr][0], acc[mf][nfr][1]);
                *(float2*)(p + (size_t)(cout + 8) * HWSZ) = make_float2(acc[mf][nfr][2], acc[mf][nfr][3]);
            }
        }
        __syncthreads();
    }
}

// ---------------------------------------------------------------------------
extern "C" void kernel_launch(void* const* d_in, const int* in_sizes, int n_in,
                              void* d_out, int out_size) {
    const float* x      = (const float*)d_in[0];
    const float* weight = (const float*)d_in[1];
    const float* bias   = (const float*)d_in[2];
    const float* vinit  = (const float*)d_in[3];
    float* out = (float*)d_out;

    cudaFuncSetAttribute(gram_mma,
                         cudaFuncAttributeMaxDynamicSharedMemorySize, G_SMEM);
    cudaFuncSetAttribute(apply_mma,
                         cudaFuncAttributeMaxDynamicSharedMemorySize, AP_SMEM);

    gram_mma<<<GR, 128, G_SMEM>>>(x);
    reduce_kernel<<<257, 128>>>();
    eigen_kernel<<<1, 256>>>(weight, bias, vinit);
    apply_mma<<<GA, 128, AP_SMEM>>>(x, out);
}